// round 9
// baseline (speedup 1.0000x reference)
#include <cuda_runtime.h>
#include <cstdint>

// ---------------- problem constants ----------------
#define N_NODES 50000
#define E_MAX   800000
#define Q_MAX   400000
constexpr int CIN = 256;   // input channels
constexpr int C1  = 128;   // hidden channels
constexpr int C2  = 64;    // output channels

// ---------------- device scratch (static; no allocs allowed) ----------------
__device__ int g_is64;                                  // 1 if index buffers are int64
__device__ __align__(16) int   g_src   [E_MAX];         // sanitized edge src
__device__ __align__(16) int   g_dst   [E_MAX];         // sanitized edge dst
__device__ __align__(16) int   g_qa    [Q_MAX];         // sanitized query endpoint a
__device__ __align__(16) int   g_qb    [Q_MAX];         // sanitized query endpoint b
__device__ __align__(16) int   g_deg   [N_NODES];       // in-degree (real edges only)
__device__ __align__(16) int   g_off   [N_NODES + 1];   // CSR offsets
__device__ __align__(16) int   g_cur   [N_NODES];       // fill cursors
__device__ __align__(16) int   g_srcidx[E_MAX];         // CSR column (src) indices
__device__ __align__(16) float g_dinv  [N_NODES];
__device__ __align__(16) float g_hs1[(size_t)N_NODES * C1];  // dinv * (x @ W1)
__device__ __align__(16) float g_h  [(size_t)N_NODES * C1];  // relu layer-1 output
__device__ __align__(16) float g_hs2[(size_t)N_NODES * C2];  // dinv * (h @ W2)
__device__ __align__(16) float g_z  [(size_t)N_NODES * C2];  // layer-2 output

__device__ __forceinline__ int clamp_idx(long long v) {
    if (v < 0) v = 0;
    if (v >= N_NODES) v = N_NODES - 1;
    return (int)v;
}

// ---------------- dtype detection: int64 buffers have zero high words ----------------
// Inspect int32 positions 1,3,...,63 of the edge buffer. If the data is int64
// (little-endian, values < 2^31) these are all zero. If the data is really
// int32, these are 32 random node ids in [0, 50000) -> all-zero is ~impossible.
__global__ void detect_kernel(const int* __restrict__ ei32) {
    int lane = threadIdx.x;              // 0..31
    int v = ei32[2 * lane + 1];
    unsigned nz = __ballot_sync(0xffffffffu, v != 0);
    if (lane == 0) g_is64 = (nz == 0u) ? 1 : 0;
}

// ---------------- zero degree ----------------
__global__ void zero_deg_kernel() {
    int i = blockIdx.x * blockDim.x + threadIdx.x;
    if (i < N_NODES) g_deg[i] = 0;
}

// ---------------- normalize edges (either dtype) + degree count ----------------
__global__ void convert_edges_kernel(const void* __restrict__ ei, int E) {
    int e = blockIdx.x * blockDim.x + threadIdx.x;
    if (e >= E) return;
    int s, d;
    if (g_is64) {
        const long long* p = (const long long*)ei;
        s = clamp_idx(p[e]);
        d = clamp_idx(p[E + e]);
    } else {
        const int* p = (const int*)ei;
        s = clamp_idx(p[e]);
        d = clamp_idx(p[E + e]);
    }
    g_src[e] = s;
    g_dst[e] = d;
    atomicAdd(&g_deg[d], 1);
}

// ---------------- normalize queries (pos then neg concatenated) ----------------
__global__ void convert_queries_kernel(const void* __restrict__ pos, const void* __restrict__ neg,
                                       int Ep, int En) {
    int i = blockIdx.x * blockDim.x + threadIdx.x;
    if (i >= Ep + En) return;
    int a, b;
    if (g_is64) {
        if (i < Ep) {
            const long long* p = (const long long*)pos;
            a = clamp_idx(p[i]);
            b = clamp_idx(p[Ep + i]);
        } else {
            const long long* p = (const long long*)neg;
            a = clamp_idx(p[i - Ep]);
            b = clamp_idx(p[En + i - Ep]);
        }
    } else {
        if (i < Ep) {
            const int* p = (const int*)pos;
            a = clamp_idx(p[i]);
            b = clamp_idx(p[Ep + i]);
        } else {
            const int* p = (const int*)neg;
            a = clamp_idx(p[i - Ep]);
            b = clamp_idx(p[En + i - Ep]);
        }
    }
    g_qa[i] = a;
    g_qb[i] = b;
}

__global__ void dinv_kernel() {
    int n = blockIdx.x * blockDim.x + threadIdx.x;
    if (n < N_NODES) g_dinv[n] = rsqrtf((float)(g_deg[n] + 1));  // +1 self-loop
}

// ---------------- exclusive scan of g_deg -> g_off / g_cur (single block, 1024 threads) ----------------
__global__ void __launch_bounds__(1024) scan_kernel() {
    __shared__ int wsum[32];
    __shared__ int s_carry;
    const int tid  = threadIdx.x;
    const int lane = tid & 31;
    const int wid  = tid >> 5;
    if (tid == 0) s_carry = 0;
    __syncthreads();

    for (int base = 0; base < N_NODES; base += 1024) {
        int i = base + tid;
        int v = (i < N_NODES) ? g_deg[i] : 0;
        int inc = v;
#pragma unroll
        for (int o = 1; o < 32; o <<= 1) {
            int t = __shfl_up_sync(0xffffffffu, inc, o);
            if (lane >= o) inc += t;
        }
        if (lane == 31) wsum[wid] = inc;
        __syncthreads();
        if (wid == 0) {
            int w = wsum[lane];
            int winc = w;
#pragma unroll
            for (int o = 1; o < 32; o <<= 1) {
                int t = __shfl_up_sync(0xffffffffu, winc, o);
                if (lane >= o) winc += t;
            }
            wsum[lane] = winc;
        }
        __syncthreads();
        int excl = s_carry + ((wid > 0) ? wsum[wid - 1] : 0) + inc - v;
        if (i < N_NODES) { g_off[i] = excl; g_cur[i] = excl; }
        int chunk_total = wsum[31];
        __syncthreads();
        if (tid == 0) s_carry += chunk_total;
        __syncthreads();
    }
    if (threadIdx.x == 0) g_off[N_NODES] = s_carry;
}

// ---------------- CSR bucket fill (int atomics only) ----------------
__global__ void fill_kernel(int E) {
    int e = blockIdx.x * blockDim.x + threadIdx.x;
    if (e < E) {
        int pos = atomicAdd(&g_cur[g_dst[e]], 1);
        g_srcidx[pos] = g_src[e];
    }
}

// ---------------- tiled SGEMM: out[m, n] = dinv[m] * sum_k A[m,k] * W[k,n] ----------------
template <int N, int K>
__global__ void __launch_bounds__(256)
gemm_scaled(const float* __restrict__ A, const float* __restrict__ W,
            const float* __restrict__ dinv, float* __restrict__ out, int M) {
    constexpr int BM = 128, BK = 16;
    constexpr int TM = 8;
    constexpr int TN = N / 16;           // 8 for N=128, 4 for N=64
    __shared__ float As[BK][BM];
    __shared__ float Bs[BK][N];

    const int tid  = threadIdx.x;
    const int row0 = blockIdx.x * BM;
    const int tm   = (tid / 16) * TM;
    const int tn   = (tid % 16) * TN;

    float acc[TM][TN];
#pragma unroll
    for (int i = 0; i < TM; i++)
#pragma unroll
        for (int j = 0; j < TN; j++) acc[i][j] = 0.f;

    for (int k0 = 0; k0 < K; k0 += BK) {
#pragma unroll
        for (int l = 0; l < 2; l++) {
            int f  = tid + l * 256;
            int r  = f / 4;
            int cs = (f % 4) * 4;
            float4 v = make_float4(0.f, 0.f, 0.f, 0.f);
            int gr = row0 + r;
            if (gr < M) v = *reinterpret_cast<const float4*>(&A[(size_t)gr * K + k0 + cs]);
            As[cs + 0][r] = v.x;
            As[cs + 1][r] = v.y;
            As[cs + 2][r] = v.z;
            As[cs + 3][r] = v.w;
        }
        constexpr int BF4 = BK * N / 4;
#pragma unroll
        for (int f = tid; f < BF4; f += 256) {
            int r = f / (N / 4);
            int c = (f % (N / 4)) * 4;
            *reinterpret_cast<float4*>(&Bs[r][c]) =
                *reinterpret_cast<const float4*>(&W[(size_t)(k0 + r) * N + c]);
        }
        __syncthreads();

#pragma unroll
        for (int kk = 0; kk < BK; kk++) {
            float a[TM], b[TN];
#pragma unroll
            for (int i = 0; i < TM; i += 4)
                *reinterpret_cast<float4*>(&a[i]) = *reinterpret_cast<float4*>(&As[kk][tm + i]);
#pragma unroll
            for (int j = 0; j < TN; j += 4)
                *reinterpret_cast<float4*>(&b[j]) = *reinterpret_cast<float4*>(&Bs[kk][tn + j]);
#pragma unroll
            for (int i = 0; i < TM; i++)
#pragma unroll
                for (int j = 0; j < TN; j++) acc[i][j] += a[i] * b[j];
        }
        __syncthreads();
    }

#pragma unroll
    for (int i = 0; i < TM; i++) {
        int gr = row0 + tm + i;
        if (gr >= M) continue;
        float s = dinv[gr];
#pragma unroll
        for (int j = 0; j < TN; j += 4) {
            float4 v;
            v.x = acc[i][j + 0] * s;
            v.y = acc[i][j + 1] * s;
            v.z = acc[i][j + 2] * s;
            v.w = acc[i][j + 3] * s;
            *reinterpret_cast<float4*>(&out[(size_t)gr * N + tn + j]) = v;
        }
    }
}

// ---------------- gather + combine, C=128: one warp per node, float4 per lane ----------------
template <bool RELU>
__global__ void gather128_kernel(const float* __restrict__ hs, float* __restrict__ out,
                                 const float* __restrict__ bias) {
    int gw   = (blockIdx.x * blockDim.x + threadIdx.x) >> 5;
    int lane = threadIdx.x & 31;
    if (gw >= N_NODES) return;
    const int s = g_off[gw];
    const int e = g_off[gw + 1];

    // self-loop contribution
    float4 acc = *reinterpret_cast<const float4*>(&hs[(size_t)gw * C1 + lane * 4]);

    int k = s;
    for (; k + 4 <= e; k += 4) {
        int s0 = g_srcidx[k + 0];
        int s1 = g_srcidx[k + 1];
        int s2 = g_srcidx[k + 2];
        int s3 = g_srcidx[k + 3];
        float4 v0 = *reinterpret_cast<const float4*>(&hs[(size_t)s0 * C1 + lane * 4]);
        float4 v1 = *reinterpret_cast<const float4*>(&hs[(size_t)s1 * C1 + lane * 4]);
        float4 v2 = *reinterpret_cast<const float4*>(&hs[(size_t)s2 * C1 + lane * 4]);
        float4 v3 = *reinterpret_cast<const float4*>(&hs[(size_t)s3 * C1 + lane * 4]);
        acc.x += v0.x + v1.x + v2.x + v3.x;
        acc.y += v0.y + v1.y + v2.y + v3.y;
        acc.z += v0.z + v1.z + v2.z + v3.z;
        acc.w += v0.w + v1.w + v2.w + v3.w;
    }
    for (; k < e; k++) {
        int sk = g_srcidx[k];
        float4 v = *reinterpret_cast<const float4*>(&hs[(size_t)sk * C1 + lane * 4]);
        acc.x += v.x; acc.y += v.y; acc.z += v.z; acc.w += v.w;
    }

    float  d = g_dinv[gw];
    float4 b = *reinterpret_cast<const float4*>(&bias[lane * 4]);
    float4 o;
    o.x = d * acc.x + b.x;
    o.y = d * acc.y + b.y;
    o.z = d * acc.z + b.z;
    o.w = d * acc.w + b.w;
    if (RELU) {
        o.x = fmaxf(o.x, 0.f); o.y = fmaxf(o.y, 0.f);
        o.z = fmaxf(o.z, 0.f); o.w = fmaxf(o.w, 0.f);
    }
    *reinterpret_cast<float4*>(&out[(size_t)gw * C1 + lane * 4]) = o;
}

// ---------------- gather + combine, C=64: one warp per node, float2 per lane ----------------
template <bool RELU>
__global__ void gather64_kernel(const float* __restrict__ hs, float* __restrict__ out,
                                const float* __restrict__ bias) {
    int gw   = (blockIdx.x * blockDim.x + threadIdx.x) >> 5;
    int lane = threadIdx.x & 31;
    if (gw >= N_NODES) return;
    const int s = g_off[gw];
    const int e = g_off[gw + 1];

    float2 acc = *reinterpret_cast<const float2*>(&hs[(size_t)gw * C2 + lane * 2]);

    int k = s;
    for (; k + 4 <= e; k += 4) {
        int s0 = g_srcidx[k + 0];
        int s1 = g_srcidx[k + 1];
        int s2 = g_srcidx[k + 2];
        int s3 = g_srcidx[k + 3];
        float2 v0 = *reinterpret_cast<const float2*>(&hs[(size_t)s0 * C2 + lane * 2]);
        float2 v1 = *reinterpret_cast<const float2*>(&hs[(size_t)s1 * C2 + lane * 2]);
        float2 v2 = *reinterpret_cast<const float2*>(&hs[(size_t)s2 * C2 + lane * 2]);
        float2 v3 = *reinterpret_cast<const float2*>(&hs[(size_t)s3 * C2 + lane * 2]);
        acc.x += v0.x + v1.x + v2.x + v3.x;
        acc.y += v0.y + v1.y + v2.y + v3.y;
    }
    for (; k < e; k++) {
        int sk = g_srcidx[k];
        float2 v = *reinterpret_cast<const float2*>(&hs[(size_t)sk * C2 + lane * 2]);
        acc.x += v.x; acc.y += v.y;
    }

    float  d = g_dinv[gw];
    float2 b = *reinterpret_cast<const float2*>(&bias[lane * 2]);
    float2 o;
    o.x = d * acc.x + b.x;
    o.y = d * acc.y + b.y;
    if (RELU) { o.x = fmaxf(o.x, 0.f); o.y = fmaxf(o.y, 0.f); }
    *reinterpret_cast<float2*>(&out[(size_t)gw * C2 + lane * 2]) = o;
}

// ---------------- logits: out[e] = dot(z[qa], z[qb]) over C2=64 dims ----------------
__global__ void logits_kernel(int Q, const float* __restrict__ z, float* __restrict__ out) {
    long long idx = (long long)blockIdx.x * blockDim.x + threadIdx.x;
    long long e = idx / 16;
    int j       = (int)(idx % 16);
    if (e >= Q) return;
    int a = g_qa[e];
    int b = g_qb[e];
    float4 va = *reinterpret_cast<const float4*>(&z[(size_t)a * C2 + j * 4]);
    float4 vb = *reinterpret_cast<const float4*>(&z[(size_t)b * C2 + j * 4]);
    float d = va.x * vb.x + va.y * vb.y + va.z * vb.z + va.w * vb.w;
#pragma unroll
    for (int off = 8; off > 0; off >>= 1)
        d += __shfl_xor_sync(0xffffffffu, d, off, 16);
    if (j == 0) out[e] = d;
}

// ---------------- launch ----------------
extern "C" void kernel_launch(void* const* d_in, const int* in_sizes, int n_in,
                              void* d_out, int out_size) {
    const float* x   = (const float*)d_in[0];
    const void*  ei  = d_in[1];
    const void*  pos = d_in[2];
    const void*  neg = d_in[3];
    const float* W1  = (const float*)d_in[4];
    const float* b1  = (const float*)d_in[5];
    const float* W2  = (const float*)d_in[6];
    const float* b2  = (const float*)d_in[7];
    float* out = (float*)d_out;

    const int E  = in_sizes[1] / 2;   // 800000
    const int Ep = in_sizes[2] / 2;   // 200000
    const int En = in_sizes[3] / 2;   // 200000
    const int Q  = Ep + En;
    const int M  = N_NODES;

    float *hs1, *h, *hs2, *z, *dinv;
    cudaGetSymbolAddress((void**)&hs1,  g_hs1);
    cudaGetSymbolAddress((void**)&h,    g_h);
    cudaGetSymbolAddress((void**)&hs2,  g_hs2);
    cudaGetSymbolAddress((void**)&z,    g_z);
    cudaGetSymbolAddress((void**)&dinv, g_dinv);

    // ---- dtype detect + normalize indices + CSR build ----
    detect_kernel<<<1, 32>>>((const int*)ei);
    zero_deg_kernel<<<(N_NODES + 255) / 256, 256>>>();
    convert_edges_kernel<<<(E + 255) / 256, 256>>>(ei, E);
    convert_queries_kernel<<<(Q + 255) / 256, 256>>>(pos, neg, Ep, En);
    dinv_kernel<<<(N_NODES + 255) / 256, 256>>>();
    scan_kernel<<<1, 1024>>>();
    fill_kernel<<<(E + 255) / 256, 256>>>(E);

    // ---- layer 1 ----
    gemm_scaled<C1, CIN><<<(M + 127) / 128, 256>>>(x, W1, dinv, hs1, M);
    gather128_kernel<true><<<(N_NODES * 32 + 255) / 256, 256>>>(hs1, h, b1);

    // ---- layer 2 ----
    gemm_scaled<C2, C1><<<(M + 127) / 128, 256>>>(h, W2, dinv, hs2, M);
    gather64_kernel<false><<<(N_NODES * 32 + 255) / 256, 256>>>(hs2, z, b2);

    // ---- logits ----
    {
        long long tot = (long long)Q * 16;
        int blocks = (int)((tot + 255) / 256);
        logits_kernel<<<blocks, 256>>>(Q, z, out);
    }
}